// round 1
// baseline (speedup 1.0000x reference)
#include <cuda_runtime.h>
#include <cfloat>

// Problem dims (fixed by setup_inputs): N=4, T=24, C=4, H=W=256
#define N_ 4
#define T_ 24
#define C_ 4
#define HW 65536          // 256*256
#define HW4 16384         // HW/4
#define NPLANES (N_*T_*C_)   // 384
#define NIMG (N_*T_)         // 96
#define OUT_ELEMS (NPLANES*HW)       // 25165824
#define PAIR_STRIDE (2*HW)           // per (n,t) in x_pairs

__device__ float g_minv[NPLANES];
__device__ float g_inv[NPLANES];
__device__ int   g_tidx[N_];

// ---------------------------------------------------------------------------
// K0: argmin_t |182 - dates[n,t]| (first occurrence), 4 threads do everything.
// ---------------------------------------------------------------------------
__global__ void k_tidx(const int* __restrict__ dates) {
    int n = threadIdx.x;
    if (n < N_) {
        int best = 0;
        int bd = abs(182 - dates[n * T_]);
        #pragma unroll
        for (int t = 1; t < T_; t++) {
            int d = abs(182 - dates[n * T_ + t]);
            if (d < bd) { bd = d; best = t; }
        }
        g_tidx[n] = best;
    }
}

// ---------------------------------------------------------------------------
// K1: fused per-plane min/max reduction + translation-bilinear warp.
// One block per (n,t,c) plane. Translation-only warp => constant integer
// shift (DX,DY) + constant 2x2 blend weights per image.
// ---------------------------------------------------------------------------
__global__ __launch_bounds__(512) void k_minmax_translate(
    const float* __restrict__ x,
    const float* __restrict__ thetas,
    float* __restrict__ out)
{
    const int plane = blockIdx.x;        // n*T*C + t*C + c
    const int b = plane >> 2;            // image index (C=4)
    const float* __restrict__ src = x + (size_t)plane * HW;
    float* __restrict__ dst = out + (size_t)plane * HW;

    const float tx = thetas[2 * b + 0];
    const float ty = thetas[2 * b + 1];
    const float fDX = floorf(-tx);
    const float fDY = floorf(-ty);
    const int DX = (int)fDX;
    const int DY = (int)fDY;
    const float wx = -tx - fDX;          // in [0,1)
    const float wy = -ty - fDY;
    const float w00 = (1.f - wy) * (1.f - wx);
    const float w01 = (1.f - wy) * wx;
    const float w10 = wy * (1.f - wx);
    const float w11 = wy * wx;

    float vmin = FLT_MAX, vmax = -FLT_MAX;
    const int tid = threadIdx.x;
    const float4* __restrict__ src4 = reinterpret_cast<const float4*>(src);
    float4* __restrict__ dst4 = reinterpret_cast<float4*>(dst);

    for (int q = tid; q < HW4; q += 512) {
        // ---- min/max path (linear, vectorized) ----
        float4 v = __ldg(src4 + q);
        vmin = fminf(vmin, fminf(fminf(v.x, v.y), fminf(v.z, v.w)));
        vmax = fmaxf(vmax, fmaxf(fmaxf(v.x, v.y), fmaxf(v.z, v.w)));

        // ---- translate path (constant shift + 2x2 blend) ----
        const int idx = q << 2;
        const int i = idx >> 8;
        const int j = idx & 255;
        const int sy0 = i + DY;
        const int sy1 = sy0 + 1;
        const bool vy0 = ((unsigned)sy0 < 256u);
        const bool vy1 = ((unsigned)sy1 < 256u);
        const float* __restrict__ r0 = src + sy0 * 256;
        const float* __restrict__ r1 = src + sy1 * 256;

        float o[4];
        #pragma unroll
        for (int k = 0; k < 4; k++) {
            const int sx0 = j + k + DX;
            const int sx1 = sx0 + 1;
            const bool vx0 = ((unsigned)sx0 < 256u);
            const bool vx1 = ((unsigned)sx1 < 256u);
            const float a = (vy0 && vx0) ? __ldg(r0 + sx0) : 0.f;
            const float bb = (vy0 && vx1) ? __ldg(r0 + sx1) : 0.f;
            const float cc = (vy1 && vx0) ? __ldg(r1 + sx0) : 0.f;
            const float dd = (vy1 && vx1) ? __ldg(r1 + sx1) : 0.f;
            o[k] = w00 * a + w01 * bb + w10 * cc + w11 * dd;
        }
        dst4[q] = make_float4(o[0], o[1], o[2], o[3]);
    }

    // ---- block min/max reduction ----
    #pragma unroll
    for (int off = 16; off; off >>= 1) {
        vmin = fminf(vmin, __shfl_xor_sync(0xffffffffu, vmin, off));
        vmax = fmaxf(vmax, __shfl_xor_sync(0xffffffffu, vmax, off));
    }
    __shared__ float smin[16], smax[16];
    const int w = tid >> 5, l = tid & 31;
    if (l == 0) { smin[w] = vmin; smax[w] = vmax; }
    __syncthreads();
    if (tid == 0) {
        float m = smin[0], M = smax[0];
        #pragma unroll
        for (int k = 1; k < 16; k++) {
            m = fminf(m, smin[k]);
            M = fmaxf(M, smax[k]);
        }
        g_minv[plane] = m;
        g_inv[plane] = 1.f / (M - m + 1e-8f);
    }
}

// ---------------------------------------------------------------------------
// K2: grayscale slice on normalized channels 0..2 -> x_pairs channel 0.
// s = sum_c GRAY[c] * (x_c - min_c) * inv_c  ==  sum_c a_c*x_c + bias
// One block per (n,t) image.
// ---------------------------------------------------------------------------
__global__ __launch_bounds__(512) void k_slice(
    const float* __restrict__ x,
    float* __restrict__ xp)
{
    const int p = blockIdx.x;            // n*T + t
    const int pb = p * C_;
    const float a0 = 0.299f * g_inv[pb + 0];
    const float a1 = 0.587f * g_inv[pb + 1];
    const float a2 = 0.114f * g_inv[pb + 2];
    const float bias = -(a0 * g_minv[pb + 0] + a1 * g_minv[pb + 1] + a2 * g_minv[pb + 2]);

    const float4* __restrict__ c0 = reinterpret_cast<const float4*>(x + (size_t)pb * HW);
    const float4* __restrict__ c1 = c0 + HW4;
    const float4* __restrict__ c2 = c1 + HW4;
    float4* __restrict__ dst = reinterpret_cast<float4*>(xp + (size_t)p * PAIR_STRIDE);

    for (int q = threadIdx.x; q < HW4; q += 512) {
        const float4 v0 = __ldg(c0 + q);
        const float4 v1 = __ldg(c1 + q);
        const float4 v2 = __ldg(c2 + q);
        float4 o;
        o.x = a0 * v0.x + a1 * v1.x + a2 * v2.x + bias;
        o.y = a0 * v0.y + a1 * v1.y + a2 * v2.y + bias;
        o.z = a0 * v0.z + a1 * v1.z + a2 * v2.z + bias;
        o.w = a0 * v0.w + a1 * v1.w + a2 * v2.w + bias;
        dst[q] = o;
    }
}

// ---------------------------------------------------------------------------
// K3: broadcast reference slice -> x_pairs channel 1 for every t.
// ---------------------------------------------------------------------------
__global__ __launch_bounds__(512) void k_ref(float* __restrict__ xp)
{
    const int p = blockIdx.x;            // n*T + t
    const int n = p / T_;
    const int tref = g_tidx[n];
    const float4* __restrict__ src = reinterpret_cast<const float4*>(
        xp + ((size_t)n * T_ + tref) * PAIR_STRIDE);
    float4* __restrict__ dst = reinterpret_cast<float4*>(
        xp + (size_t)p * PAIR_STRIDE + HW);
    for (int q = threadIdx.x; q < HW4; q += 512) {
        dst[q] = __ldg(src + q);
    }
}

// ---------------------------------------------------------------------------
extern "C" void kernel_launch(void* const* d_in, const int* in_sizes, int n_in,
                              void* d_out, int out_size) {
    const float* x      = (const float*)d_in[0];
    const int*   dates  = (const int*)d_in[1];
    const float* thetas = (const float*)d_in[2];
    float* out = (float*)d_out;             // (n,t,c,h,w)
    float* xp  = out + OUT_ELEMS;           // x_pairs (n,t,2,h,w)

    k_tidx<<<1, 32>>>(dates);
    k_minmax_translate<<<NPLANES, 512>>>(x, thetas, out);
    k_slice<<<NIMG, 512>>>(x, xp);
    k_ref<<<NIMG, 512>>>(xp);
}

// round 2
// speedup vs baseline: 1.4873x; 1.4873x over previous
#include <cuda_runtime.h>
#include <cfloat>

// Problem dims (fixed): N=4, T=24, C=4, H=W=256
#define N_ 4
#define T_ 24
#define C_ 4
#define HW 65536
#define NPLANES (N_*T_*C_)   // 384
#define NIMG (N_*T_)         // 96
#define OUT_ELEMS (NPLANES*HW)
#define PAIR_STRIDE (2*HW)

#define ROWS 16              // K1 rows per slab
#define SLABS (256/ROWS)     // 16
#define SROWS 32             // K2 rows per slab
#define SSLABS (256/SROWS)   // 8

__device__ unsigned g_min_enc[NPLANES];
__device__ unsigned g_max_enc[NPLANES];
__device__ int      g_tidx[N_];

// Monotonic float <-> uint encoding for atomicMin/Max
__device__ __forceinline__ unsigned encf(float f) {
    unsigned u = __float_as_uint(f);
    return (u & 0x80000000u) ? ~u : (u | 0x80000000u);
}
__device__ __forceinline__ float decf(unsigned e) {
    return (e & 0x80000000u) ? __uint_as_float(e ^ 0x80000000u)
                             : __uint_as_float(~e);
}

// ---------------------------------------------------------------------------
// K0: init min/max slots + argmin_t |182 - dates[n,t]|
// ---------------------------------------------------------------------------
__global__ void k_init(const int* __restrict__ dates) {
    const int i = blockIdx.x * blockDim.x + threadIdx.x;
    if (i < NPLANES) { g_min_enc[i] = 0xFFFFFFFFu; g_max_enc[i] = 0u; }
    if (i < N_) {
        int best = 0;
        int bd = abs(182 - dates[i * T_]);
        #pragma unroll
        for (int t = 1; t < T_; t++) {
            int d = abs(182 - dates[i * T_ + t]);
            if (d < bd) { bd = d; best = t; }
        }
        g_tidx[i] = best;
    }
}

// ---------------------------------------------------------------------------
// K1: per (plane, slab): translate via smem-staged horizontal blend +
//     partial min/max with encoded atomics. grid = 384*16 = 6144 blocks.
// ---------------------------------------------------------------------------
__global__ __launch_bounds__(256) void k_translate_minmax(
    const float* __restrict__ x,
    const float* __restrict__ thetas,
    float* __restrict__ out)
{
    __shared__ float raw[(ROWS + 1) * 256];
    __shared__ float hbuf[(ROWS + 1) * 256];
    __shared__ float smin[8], smax[8];

    const int plane = blockIdx.x >> 4;       // / SLABS
    const int slab  = blockIdx.x & (SLABS - 1);
    const int r0 = slab * ROWS;
    const int b = plane >> 2;                 // image index (C=4)
    const float* __restrict__ src = x + (size_t)plane * HW;
    float* __restrict__ dst = out + (size_t)plane * HW + (size_t)r0 * 256;

    const float tx = thetas[2 * b + 0];
    const float ty = thetas[2 * b + 1];
    const float fDX = floorf(-tx);
    const float fDY = floorf(-ty);
    const int DX = (int)fDX;
    const int DY = (int)fDY;
    const float wx = -tx - fDX;
    const float wy = -ty - fDY;
    const float wxc = 1.f - wx;
    const float wyc = 1.f - wy;
    const int tid = threadIdx.x;

    // Stage raw source rows [r0+DY, r0+DY+ROWS] (ROWS+1 rows), zero out-of-range.
    {
        const int NV = (ROWS + 1) * 64;
        for (int q = tid; q < NV; q += 256) {
            const int rr = q >> 6;
            const int c4 = q & 63;
            const int gr = r0 + DY + rr;
            float4 v = make_float4(0.f, 0.f, 0.f, 0.f);
            if ((unsigned)gr < 256u)
                v = __ldg(reinterpret_cast<const float4*>(src + gr * 256) + c4);
            reinterpret_cast<float4*>(raw)[q] = v;
        }
    }
    __syncthreads();

    // Build horizontal blend h[rr][j] = wxc*s[rr][j+DX] + wx*s[rr][j+DX+1]
    {
        const int NE = (ROWS + 1) * 256;
        for (int q = tid; q < NE; q += 256) {
            const int rr = q >> 8;
            const int j = q & 255;
            const int c0 = j + DX;
            const float a  = ((unsigned)c0       < 256u) ? raw[rr * 256 + c0]     : 0.f;
            const float bb = ((unsigned)(c0 + 1) < 256u) ? raw[rr * 256 + c0 + 1] : 0.f;
            hbuf[q] = wxc * a + wx * bb;
        }
    }
    __syncthreads();

    // Output: vertical blend of two h rows (aligned LDS.128), streaming store.
    {
        for (int q = tid; q < ROWS * 64; q += 256) {
            const int rr = q >> 6;
            const int c4 = q & 63;
            const float4 h0 = reinterpret_cast<const float4*>(hbuf + rr * 256)[c4];
            const float4 h1 = reinterpret_cast<const float4*>(hbuf + (rr + 1) * 256)[c4];
            float4 o;
            o.x = wyc * h0.x + wy * h1.x;
            o.y = wyc * h0.y + wy * h1.y;
            o.z = wyc * h0.z + wy * h1.z;
            o.w = wyc * h0.w + wy * h1.w;
            __stcs(reinterpret_cast<float4*>(dst) + q, o);
        }
    }

    // Partial min/max over raw plane rows [r0, r0+ROWS) (mostly L1/L2 hits).
    float vmin = FLT_MAX, vmax = -FLT_MAX;
    {
        const float4* __restrict__ s4 =
            reinterpret_cast<const float4*>(src + (size_t)r0 * 256);
        for (int q = tid; q < ROWS * 64; q += 256) {
            const float4 v = __ldg(s4 + q);
            vmin = fminf(vmin, fminf(fminf(v.x, v.y), fminf(v.z, v.w)));
            vmax = fmaxf(vmax, fmaxf(fmaxf(v.x, v.y), fmaxf(v.z, v.w)));
        }
    }
    #pragma unroll
    for (int off = 16; off; off >>= 1) {
        vmin = fminf(vmin, __shfl_xor_sync(0xffffffffu, vmin, off));
        vmax = fmaxf(vmax, __shfl_xor_sync(0xffffffffu, vmax, off));
    }
    const int w = tid >> 5, l = tid & 31;
    if (l == 0) { smin[w] = vmin; smax[w] = vmax; }
    __syncthreads();
    if (tid == 0) {
        float m = smin[0], M = smax[0];
        #pragma unroll
        for (int k = 1; k < 8; k++) {
            m = fminf(m, smin[k]);
            M = fmaxf(M, smax[k]);
        }
        atomicMin(&g_min_enc[plane], encf(m));
        atomicMax(&g_max_enc[plane], encf(M));
    }
}

// ---------------------------------------------------------------------------
// K2: fused grayscale slice (ch0) + reference slice broadcast (ch1).
//     Ref slice recomputed from x[n, tref] (L2-hot, read 24x per n).
//     grid = 96*8 = 768 blocks.
// ---------------------------------------------------------------------------
__global__ __launch_bounds__(256) void k_slice_ref(
    const float* __restrict__ x,
    float* __restrict__ xp)
{
    const int p    = blockIdx.x >> 3;        // / SSLABS, (n,t) image
    const int slab = blockIdx.x & (SSLABS - 1);
    const int n = p / T_;
    const int r0 = slab * SROWS;
    const int tref = g_tidx[n];
    const int pref = n * T_ + tref;

    // own coefficients
    const int pb = p * C_;
    const float i0 = 1.f / (decf(g_max_enc[pb+0]) - decf(g_min_enc[pb+0]) + 1e-8f);
    const float i1 = 1.f / (decf(g_max_enc[pb+1]) - decf(g_min_enc[pb+1]) + 1e-8f);
    const float i2 = 1.f / (decf(g_max_enc[pb+2]) - decf(g_min_enc[pb+2]) + 1e-8f);
    const float a0 = 0.299f * i0, a1 = 0.587f * i1, a2 = 0.114f * i2;
    const float bias = -(a0 * decf(g_min_enc[pb+0]) +
                         a1 * decf(g_min_enc[pb+1]) +
                         a2 * decf(g_min_enc[pb+2]));

    // ref coefficients
    const int rb = pref * C_;
    const float j0 = 1.f / (decf(g_max_enc[rb+0]) - decf(g_min_enc[rb+0]) + 1e-8f);
    const float j1 = 1.f / (decf(g_max_enc[rb+1]) - decf(g_min_enc[rb+1]) + 1e-8f);
    const float j2 = 1.f / (decf(g_max_enc[rb+2]) - decf(g_min_enc[rb+2]) + 1e-8f);
    const float b0 = 0.299f * j0, b1 = 0.587f * j1, b2 = 0.114f * j2;
    const float rbias = -(b0 * decf(g_min_enc[rb+0]) +
                          b1 * decf(g_min_enc[rb+1]) +
                          b2 * decf(g_min_enc[rb+2]));

    const size_t roff = (size_t)r0 * 256;
    const float4* __restrict__ c0 = reinterpret_cast<const float4*>(x + (size_t)pb * HW + roff);
    const float4* __restrict__ c1 = reinterpret_cast<const float4*>(x + (size_t)(pb+1) * HW + roff);
    const float4* __restrict__ c2 = reinterpret_cast<const float4*>(x + (size_t)(pb+2) * HW + roff);
    const float4* __restrict__ d0 = reinterpret_cast<const float4*>(x + (size_t)rb * HW + roff);
    const float4* __restrict__ d1 = reinterpret_cast<const float4*>(x + (size_t)(rb+1) * HW + roff);
    const float4* __restrict__ d2 = reinterpret_cast<const float4*>(x + (size_t)(rb+2) * HW + roff);
    float4* __restrict__ o0 = reinterpret_cast<float4*>(xp + (size_t)p * PAIR_STRIDE + roff);
    float4* __restrict__ o1 = reinterpret_cast<float4*>(xp + (size_t)p * PAIR_STRIDE + HW + roff);

    for (int q = threadIdx.x; q < SROWS * 64; q += 256) {
        const float4 v0 = __ldg(c0 + q);
        const float4 v1 = __ldg(c1 + q);
        const float4 v2 = __ldg(c2 + q);
        float4 o;
        o.x = a0 * v0.x + a1 * v1.x + a2 * v2.x + bias;
        o.y = a0 * v0.y + a1 * v1.y + a2 * v2.y + bias;
        o.z = a0 * v0.z + a1 * v1.z + a2 * v2.z + bias;
        o.w = a0 * v0.w + a1 * v1.w + a2 * v2.w + bias;
        __stcs(o0 + q, o);

        const float4 u0 = __ldg(d0 + q);
        const float4 u1 = __ldg(d1 + q);
        const float4 u2 = __ldg(d2 + q);
        float4 r;
        r.x = b0 * u0.x + b1 * u1.x + b2 * u2.x + rbias;
        r.y = b0 * u0.y + b1 * u1.y + b2 * u2.y + rbias;
        r.z = b0 * u0.z + b1 * u1.z + b2 * u2.z + rbias;
        r.w = b0 * u0.w + b1 * u1.w + b2 * u2.w + rbias;
        __stcs(o1 + q, r);
    }
}

// ---------------------------------------------------------------------------
extern "C" void kernel_launch(void* const* d_in, const int* in_sizes, int n_in,
                              void* d_out, int out_size) {
    const float* x      = (const float*)d_in[0];
    const int*   dates  = (const int*)d_in[1];
    const float* thetas = (const float*)d_in[2];
    float* out = (float*)d_out;
    float* xp  = out + OUT_ELEMS;

    k_init<<<2, 256>>>(dates);
    k_translate_minmax<<<NPLANES * SLABS, 256>>>(x, thetas, out);
    k_slice_ref<<<NIMG * SSLABS, 256>>>(x, xp);
}

// round 3
// speedup vs baseline: 1.5933x; 1.0713x over previous
#include <cuda_runtime.h>
#include <cfloat>

// Problem dims (fixed): N=4, T=24, C=4, H=W=256
#define N_ 4
#define T_ 24
#define C_ 4
#define HW 65536
#define NPLANES (N_*T_*C_)   // 384
#define NIMG (N_*T_)         // 96
#define OUT_ELEMS (NPLANES*HW)
#define PAIR_STRIDE (2*HW)

#define ROWS 16              // K1 source rows per slab
#define SLABS (256/ROWS)     // 16
#define SROWS 32             // K2 rows per slab
#define SSLABS (256/SROWS)   // 8

// Per-slab partial min/max (plain stores; no init kernel needed)
__device__ float g_smin[NPLANES * SLABS];
__device__ float g_smax[NPLANES * SLABS];
__device__ int   g_tidx[N_];

// ---------------------------------------------------------------------------
// K1: block = (plane, slab). Stages SOURCE rows [r0, r0+ROWS] (17 rows),
// fuses min/max reduction into the staging pass, builds per-source-row
// horizontal blend in smem, then writes the dest rows whose vertical taps
// live in the staged window. Boundary rows / all-zero rows handled explicitly.
// Blocks 0..3 additionally compute argmin date index.
// ---------------------------------------------------------------------------
__global__ __launch_bounds__(256) void k_translate_minmax(
    const float* __restrict__ x,
    const int* __restrict__ dates,
    const float* __restrict__ thetas,
    float* __restrict__ out)
{
    __shared__ float raw[(ROWS + 1) * 256];
    __shared__ float hbuf[(ROWS + 1) * 256];
    __shared__ float smin[8], smax[8];

    const int plane = blockIdx.x >> 4;        // / SLABS
    const int slab  = blockIdx.x & (SLABS - 1);
    const int r0 = slab * ROWS;
    const int b = plane >> 2;                 // image index (C=4)
    const int tid = threadIdx.x;
    const float* __restrict__ src = x + (size_t)plane * HW;
    float4* __restrict__ dst4 = reinterpret_cast<float4*>(out + (size_t)plane * HW);

    // Side job: argmin_t |182 - dates[n,t]| (blocks 0..3)
    if (blockIdx.x < N_ && tid == 0) {
        const int n = blockIdx.x;
        int best = 0;
        int bd = abs(182 - dates[n * T_]);
        #pragma unroll
        for (int t = 1; t < T_; t++) {
            int d = abs(182 - dates[n * T_ + t]);
            if (d < bd) { bd = d; best = t; }
        }
        g_tidx[n] = best;
    }

    const float tx = thetas[2 * b + 0];
    const float ty = thetas[2 * b + 1];
    const float fDX = floorf(-tx);
    const float fDY = floorf(-ty);
    const int DX = (int)fDX;
    const int DY = (int)fDY;
    const float wx = -tx - fDX;
    const float wy = -ty - fDY;
    const float wxc = 1.f - wx;
    const float wyc = 1.f - wy;

    // ---- Stage source rows r0..r0+ROWS, fused min/max over rows rr<ROWS ----
    float vmin = FLT_MAX, vmax = -FLT_MAX;
    for (int q = tid; q < (ROWS + 1) * 64; q += 256) {
        const int rr = q >> 6;
        const int c4 = q & 63;
        const int gr = r0 + rr;
        float4 v = make_float4(0.f, 0.f, 0.f, 0.f);
        if (gr < 256)
            v = __ldg(reinterpret_cast<const float4*>(src + gr * 256) + c4);
        reinterpret_cast<float4*>(raw)[q] = v;
        if (rr < ROWS) {
            vmin = fminf(vmin, fminf(fminf(v.x, v.y), fminf(v.z, v.w)));
            vmax = fmaxf(vmax, fmaxf(fmaxf(v.x, v.y), fmaxf(v.z, v.w)));
        }
    }
    __syncthreads();

    // ---- Horizontal blend: h[rr][j] = wxc*raw[rr][j+DX] + wx*raw[rr][j+DX+1]
    for (int q = tid; q < (ROWS + 1) * 256; q += 256) {
        const int rr = q >> 8;
        const int j = q & 255;
        const int c0 = j + DX;
        const float a  = ((unsigned)c0       < 256u) ? raw[rr * 256 + c0]     : 0.f;
        const float bb = ((unsigned)(c0 + 1) < 256u) ? raw[rr * 256 + c0 + 1] : 0.f;
        hbuf[q] = wxc * a + wx * bb;
    }
    __syncthreads();

    // ---- Main output: dest rows i in [r0-DY, r0+ROWS-DY) clipped to [0,256)
    {
        const int istart = max(0, r0 - DY);
        const int iend   = min(256, r0 + ROWS - DY);
        const int nrows  = iend - istart;
        const float4* __restrict__ h4 = reinterpret_cast<const float4*>(hbuf);
        for (int q = tid; q < nrows * 64; q += 256) {
            const int rr = q >> 6;
            const int c4 = q & 63;
            const int i = istart + rr;
            const int l0 = i + DY - r0;            // in [0, ROWS)
            const float4 h0 = h4[l0 * 64 + c4];
            const float4 h1 = h4[(l0 + 1) * 64 + c4];
            float4 o;
            o.x = wyc * h0.x + wy * h1.x;
            o.y = wyc * h0.y + wy * h1.y;
            o.z = wyc * h0.z + wy * h1.z;
            o.w = wyc * h0.w + wy * h1.w;
            __stcs(dst4 + i * 64 + c4, o);
        }
    }

    // ---- Boundary row i = -DY-1 (only valid tap is source row 0, weight wy)
    if (r0 == 0 && DY <= -1) {
        const int i = -DY - 1;
        if (i < 256 && tid < 64) {
            const float4 h0 = reinterpret_cast<const float4*>(hbuf)[tid];
            float4 o;
            o.x = wy * h0.x; o.y = wy * h0.y; o.z = wy * h0.z; o.w = wy * h0.w;
            __stcs(dst4 + i * 64 + tid, o);
        }
    }

    // ---- Zero-fill: rows of this slab that no block computes
    {
        const int lo = max(0, -DY - 1);              // first covered row
        const int hi = min(256, 256 - DY);           // one past last covered
        const float4 z = make_float4(0.f, 0.f, 0.f, 0.f);
        for (int q = tid; q < ROWS * 64; q += 256) {
            const int r = r0 + (q >> 6);
            if (r < lo || r >= hi)
                __stcs(dst4 + r * 64 + (q & 63), z);
        }
    }

    // ---- Block min/max reduction -> per-slab partial (plain store) ----
    #pragma unroll
    for (int off = 16; off; off >>= 1) {
        vmin = fminf(vmin, __shfl_xor_sync(0xffffffffu, vmin, off));
        vmax = fmaxf(vmax, __shfl_xor_sync(0xffffffffu, vmax, off));
    }
    const int w = tid >> 5, l = tid & 31;
    if (l == 0) { smin[w] = vmin; smax[w] = vmax; }
    __syncthreads();
    if (tid == 0) {
        float m = smin[0], M = smax[0];
        #pragma unroll
        for (int k = 1; k < 8; k++) {
            m = fminf(m, smin[k]);
            M = fmaxf(M, smax[k]);
        }
        g_smin[plane * SLABS + slab] = m;
        g_smax[plane * SLABS + slab] = M;
    }
}

// ---------------------------------------------------------------------------
// K2: fused grayscale slice (ch0) + reference slice broadcast (ch1).
// Prologue reduces the 16 per-slab partials for 6 channels (own 0-2, ref 0-2).
// ---------------------------------------------------------------------------
__global__ __launch_bounds__(256) void k_slice_ref(
    const float* __restrict__ x,
    float* __restrict__ xp)
{
    __shared__ float s_m[6], s_M[6];

    const int p    = blockIdx.x >> 3;        // / SSLABS  (n,t) image
    const int slab = blockIdx.x & (SSLABS - 1);
    const int n = p / T_;
    const int r0 = slab * SROWS;
    const int tref = g_tidx[n];
    const int pb = p * C_;
    const int rb = (n * T_ + tref) * C_;
    const int tid = threadIdx.x;

    if (tid < 6) {
        const int pl = (tid < 3) ? (pb + tid) : (rb + tid - 3);
        float m = FLT_MAX, M = -FLT_MAX;
        #pragma unroll
        for (int s = 0; s < SLABS; s++) {
            m = fminf(m, g_smin[pl * SLABS + s]);
            M = fmaxf(M, g_smax[pl * SLABS + s]);
        }
        s_m[tid] = m;
        s_M[tid] = M;
    }
    __syncthreads();

    const float a0 = 0.299f / (s_M[0] - s_m[0] + 1e-8f);
    const float a1 = 0.587f / (s_M[1] - s_m[1] + 1e-8f);
    const float a2 = 0.114f / (s_M[2] - s_m[2] + 1e-8f);
    const float bias = -(a0 * s_m[0] + a1 * s_m[1] + a2 * s_m[2]);
    const float b0 = 0.299f / (s_M[3] - s_m[3] + 1e-8f);
    const float b1 = 0.587f / (s_M[4] - s_m[4] + 1e-8f);
    const float b2 = 0.114f / (s_M[5] - s_m[5] + 1e-8f);
    const float rbias = -(b0 * s_m[3] + b1 * s_m[4] + b2 * s_m[5]);

    const size_t roff = (size_t)r0 * 256;
    const float4* __restrict__ c0 = reinterpret_cast<const float4*>(x + (size_t)pb * HW + roff);
    const float4* __restrict__ c1 = reinterpret_cast<const float4*>(x + (size_t)(pb+1) * HW + roff);
    const float4* __restrict__ c2 = reinterpret_cast<const float4*>(x + (size_t)(pb+2) * HW + roff);
    const float4* __restrict__ d0 = reinterpret_cast<const float4*>(x + (size_t)rb * HW + roff);
    const float4* __restrict__ d1 = reinterpret_cast<const float4*>(x + (size_t)(rb+1) * HW + roff);
    const float4* __restrict__ d2 = reinterpret_cast<const float4*>(x + (size_t)(rb+2) * HW + roff);
    float4* __restrict__ o0 = reinterpret_cast<float4*>(xp + (size_t)p * PAIR_STRIDE + roff);
    float4* __restrict__ o1 = reinterpret_cast<float4*>(xp + (size_t)p * PAIR_STRIDE + HW + roff);

    for (int q = tid; q < SROWS * 64; q += 256) {
        const float4 v0 = __ldg(c0 + q);
        const float4 v1 = __ldg(c1 + q);
        const float4 v2 = __ldg(c2 + q);
        float4 o;
        o.x = a0 * v0.x + a1 * v1.x + a2 * v2.x + bias;
        o.y = a0 * v0.y + a1 * v1.y + a2 * v2.y + bias;
        o.z = a0 * v0.z + a1 * v1.z + a2 * v2.z + bias;
        o.w = a0 * v0.w + a1 * v1.w + a2 * v2.w + bias;
        __stcs(o0 + q, o);

        const float4 u0 = __ldg(d0 + q);
        const float4 u1 = __ldg(d1 + q);
        const float4 u2 = __ldg(d2 + q);
        float4 r;
        r.x = b0 * u0.x + b1 * u1.x + b2 * u2.x + rbias;
        r.y = b0 * u0.y + b1 * u1.y + b2 * u2.y + rbias;
        r.z = b0 * u0.z + b1 * u1.z + b2 * u2.z + rbias;
        r.w = b0 * u0.w + b1 * u1.w + b2 * u2.w + rbias;
        __stcs(o1 + q, r);
    }
}

// ---------------------------------------------------------------------------
extern "C" void kernel_launch(void* const* d_in, const int* in_sizes, int n_in,
                              void* d_out, int out_size) {
    const float* x      = (const float*)d_in[0];
    const int*   dates  = (const int*)d_in[1];
    const float* thetas = (const float*)d_in[2];
    float* out = (float*)d_out;
    float* xp  = out + OUT_ELEMS;

    k_translate_minmax<<<NPLANES * SLABS, 256>>>(x, dates, thetas, out);
    k_slice_ref<<<NIMG * SSLABS, 256>>>(x, xp);
}

// round 4
// speedup vs baseline: 1.6668x; 1.0461x over previous
#include <cuda_runtime.h>
#include <cfloat>

// Problem dims (fixed): N=4, T=24, C=4, H=W=256
#define N_ 4
#define T_ 24
#define C_ 4
#define HW 65536
#define NPLANES (N_*T_*C_)   // 384
#define NIMG (N_*T_)         // 96
#define OUT_ELEMS (NPLANES*HW)
#define PAIR_STRIDE (2*HW)

#define ROWS 16              // K1 source rows per slab
#define SLABS (256/ROWS)     // 16
#define SROWS 32             // K2 rows per slab
#define SSLABS (256/SROWS)   // 8

__device__ float g_smin[NPLANES * SLABS];
__device__ float g_smax[NPLANES * SLABS];
__device__ int   g_tidx[N_];

__device__ __forceinline__ float4 ld_guard(const float4* __restrict__ row, int A) {
    // A is float4 index within a 64-float4 (256-col) row; OOB -> 0 (zeros padding)
    return ((unsigned)A < 64u) ? row[A] : make_float4(0.f, 0.f, 0.f, 0.f);
}

// Horizontal blend for one staged row: output cols [4c,4c+4) need source
// elements (4A+OFF+m) and (+1). v covers cols [4A,4A+4), w covers [4A+4,4A+8).
template<int OFF>
__device__ __forceinline__ float4 hblend(const float4* __restrict__ row, int A,
                                         float wxc, float wx) {
    const float4 v = ld_guard(row, A);
    const float4 w = ld_guard(row, A + 1);
    const float e0 = (OFF == 0) ? v.x : (OFF == 1) ? v.y : (OFF == 2) ? v.z : v.w;
    const float e1 = (OFF == 0) ? v.y : (OFF == 1) ? v.z : (OFF == 2) ? v.w : w.x;
    const float e2 = (OFF == 0) ? v.z : (OFF == 1) ? v.w : (OFF == 2) ? w.x : w.y;
    const float e3 = (OFF == 0) ? v.w : (OFF == 1) ? w.x : (OFF == 2) ? w.y : w.z;
    const float e4 = (OFF == 0) ? w.x : (OFF == 1) ? w.y : (OFF == 2) ? w.z : w.w;
    float4 h;
    h.x = wxc * e0 + wx * e1;
    h.y = wxc * e1 + wx * e2;
    h.z = wxc * e2 + wx * e3;
    h.w = wxc * e3 + wx * e4;
    return h;
}

template<int OFF>
__device__ __forceinline__ void translate_body(
    const float4* __restrict__ sraw,    // [17][64]
    float4* __restrict__ dst4,
    int r0, int DXd, int DY,
    float wx, float wxc, float wy, float wyc, int tid)
{
    // Main: dest rows i in [r0-DY, r0+ROWS-DY) clipped to [0,256)
    const int istart = max(0, r0 - DY);
    const int iend   = min(256, r0 + ROWS - DY);
    const int nrows  = iend - istart;
    for (int q = tid; q < nrows * 64; q += 256) {
        const int rr = q >> 6;
        const int c4 = q & 63;
        const int i = istart + rr;
        const int l0 = i + DY - r0;          // in [0, ROWS)
        const int A = c4 + DXd;
        const float4 h0 = hblend<OFF>(sraw + l0 * 64, A, wxc, wx);
        const float4 h1 = hblend<OFF>(sraw + (l0 + 1) * 64, A, wxc, wx);
        float4 o;
        o.x = wyc * h0.x + wy * h1.x;
        o.y = wyc * h0.y + wy * h1.y;
        o.z = wyc * h0.z + wy * h1.z;
        o.w = wyc * h0.w + wy * h1.w;
        __stcs(dst4 + i * 64 + c4, o);
    }
    // Boundary row i = -DY-1 (only valid tap is source row 0, weight wy)
    if (r0 == 0 && DY <= -1) {
        const int i = -DY - 1;
        if (i < 256 && tid < 64) {
            const float4 h0 = hblend<OFF>(sraw, tid + DXd, wxc, wx);
            float4 o;
            o.x = wy * h0.x; o.y = wy * h0.y; o.z = wy * h0.z; o.w = wy * h0.w;
            __stcs(dst4 + i * 64 + tid, o);
        }
    }
}

// ---------------------------------------------------------------------------
// K1: block = (plane, slab). Stage source rows [r0, r0+ROWS] (17 rows) with
// fused min/max; translate via register-windowed blend (no hbuf pass).
// ---------------------------------------------------------------------------
__global__ __launch_bounds__(256) void k_translate_minmax(
    const float* __restrict__ x,
    const int* __restrict__ dates,
    const float* __restrict__ thetas,
    float* __restrict__ out)
{
    __shared__ float4 sraw[(ROWS + 1) * 64];
    __shared__ float smin[8], smax[8];

    const int plane = blockIdx.x >> 4;
    const int slab  = blockIdx.x & (SLABS - 1);
    const int r0 = slab * ROWS;
    const int b = plane >> 2;
    const int tid = threadIdx.x;
    const float* __restrict__ src = x + (size_t)plane * HW;
    float4* __restrict__ dst4 = reinterpret_cast<float4*>(out + (size_t)plane * HW);

    // Side job: argmin_t |182 - dates[n,t]| (blocks 0..3)
    if (blockIdx.x < N_ && tid == 0) {
        const int n = blockIdx.x;
        int best = 0;
        int bd = abs(182 - dates[n * T_]);
        #pragma unroll
        for (int t = 1; t < T_; t++) {
            int d = abs(182 - dates[n * T_ + t]);
            if (d < bd) { bd = d; best = t; }
        }
        g_tidx[n] = best;
    }

    const float tx = thetas[2 * b + 0];
    const float ty = thetas[2 * b + 1];
    const float fDX = floorf(-tx);
    const float fDY = floorf(-ty);
    const int DX = (int)fDX;
    const int DY = (int)fDY;
    const float wx = -tx - fDX;
    const float wy = -ty - fDY;
    const float wxc = 1.f - wx;
    const float wyc = 1.f - wy;
    const int DXd = DX >> 2;        // floor(DX/4)
    const int off = DX & 3;

    // ---- Stage rows r0..r0+ROWS, fused min/max over rr < ROWS ----
    float vmin = FLT_MAX, vmax = -FLT_MAX;
    for (int q = tid; q < (ROWS + 1) * 64; q += 256) {
        const int rr = q >> 6;
        const int gr = r0 + rr;
        float4 v = make_float4(0.f, 0.f, 0.f, 0.f);
        if (gr < 256)
            v = __ldg(reinterpret_cast<const float4*>(src + gr * 256) + (q & 63));
        sraw[q] = v;
        if (rr < ROWS) {
            vmin = fminf(vmin, fminf(fminf(v.x, v.y), fminf(v.z, v.w)));
            vmax = fmaxf(vmax, fmaxf(fmaxf(v.x, v.y), fmaxf(v.z, v.w)));
        }
    }
    __syncthreads();

    // ---- Translate (templated on DX & 3) ----
    switch (off) {
        case 0: translate_body<0>(sraw, dst4, r0, DXd, DY, wx, wxc, wy, wyc, tid); break;
        case 1: translate_body<1>(sraw, dst4, r0, DXd, DY, wx, wxc, wy, wyc, tid); break;
        case 2: translate_body<2>(sraw, dst4, r0, DXd, DY, wx, wxc, wy, wyc, tid); break;
        default: translate_body<3>(sraw, dst4, r0, DXd, DY, wx, wxc, wy, wyc, tid); break;
    }

    // ---- Zero-fill rows no block computes ----
    {
        const int lo = max(0, -DY - 1);
        const int hi = min(256, 256 - DY);
        const float4 z = make_float4(0.f, 0.f, 0.f, 0.f);
        for (int q = tid; q < ROWS * 64; q += 256) {
            const int r = r0 + (q >> 6);
            if (r < lo || r >= hi)
                __stcs(dst4 + r * 64 + (q & 63), z);
        }
    }

    // ---- Block min/max -> per-slab partial ----
    #pragma unroll
    for (int o = 16; o; o >>= 1) {
        vmin = fminf(vmin, __shfl_xor_sync(0xffffffffu, vmin, o));
        vmax = fmaxf(vmax, __shfl_xor_sync(0xffffffffu, vmax, o));
    }
    const int w = tid >> 5, l = tid & 31;
    if (l == 0) { smin[w] = vmin; smax[w] = vmax; }
    __syncthreads();
    if (tid == 0) {
        float m = smin[0], M = smax[0];
        #pragma unroll
        for (int k = 1; k < 8; k++) {
            m = fminf(m, smin[k]);
            M = fmaxf(M, smax[k]);
        }
        g_smin[plane * SLABS + slab] = m;
        g_smax[plane * SLABS + slab] = M;
    }
}

// ---------------------------------------------------------------------------
// K2: fused grayscale slice (ch0) + reference slice broadcast (ch1).
// ---------------------------------------------------------------------------
__global__ __launch_bounds__(256) void k_slice_ref(
    const float* __restrict__ x,
    float* __restrict__ xp)
{
    __shared__ float s_m[6], s_M[6];

    const int p    = blockIdx.x >> 3;
    const int slab = blockIdx.x & (SSLABS - 1);
    const int n = p / T_;
    const int r0 = slab * SROWS;
    const int tref = g_tidx[n];
    const int pb = p * C_;
    const int rb = (n * T_ + tref) * C_;
    const int tid = threadIdx.x;

    if (tid < 6) {
        const int pl = (tid < 3) ? (pb + tid) : (rb + tid - 3);
        float m = FLT_MAX, M = -FLT_MAX;
        #pragma unroll
        for (int s = 0; s < SLABS; s++) {
            m = fminf(m, g_smin[pl * SLABS + s]);
            M = fmaxf(M, g_smax[pl * SLABS + s]);
        }
        s_m[tid] = m;
        s_M[tid] = M;
    }
    __syncthreads();

    const float a0 = 0.299f / (s_M[0] - s_m[0] + 1e-8f);
    const float a1 = 0.587f / (s_M[1] - s_m[1] + 1e-8f);
    const float a2 = 0.114f / (s_M[2] - s_m[2] + 1e-8f);
    const float bias = -(a0 * s_m[0] + a1 * s_m[1] + a2 * s_m[2]);
    const float b0 = 0.299f / (s_M[3] - s_m[3] + 1e-8f);
    const float b1 = 0.587f / (s_M[4] - s_m[4] + 1e-8f);
    const float b2 = 0.114f / (s_M[5] - s_m[5] + 1e-8f);
    const float rbias = -(b0 * s_m[3] + b1 * s_m[4] + b2 * s_m[5]);

    const size_t roff = (size_t)r0 * 256;
    const float4* __restrict__ c0 = reinterpret_cast<const float4*>(x + (size_t)pb * HW + roff);
    const float4* __restrict__ c1 = reinterpret_cast<const float4*>(x + (size_t)(pb+1) * HW + roff);
    const float4* __restrict__ c2 = reinterpret_cast<const float4*>(x + (size_t)(pb+2) * HW + roff);
    const float4* __restrict__ d0 = reinterpret_cast<const float4*>(x + (size_t)rb * HW + roff);
    const float4* __restrict__ d1 = reinterpret_cast<const float4*>(x + (size_t)(rb+1) * HW + roff);
    const float4* __restrict__ d2 = reinterpret_cast<const float4*>(x + (size_t)(rb+2) * HW + roff);
    float4* __restrict__ o0 = reinterpret_cast<float4*>(xp + (size_t)p * PAIR_STRIDE + roff);
    float4* __restrict__ o1 = reinterpret_cast<float4*>(xp + (size_t)p * PAIR_STRIDE + HW + roff);

    #pragma unroll 2
    for (int q = tid; q < SROWS * 64; q += 256) {
        const float4 v0 = __ldcs(c0 + q);
        const float4 v1 = __ldcs(c1 + q);
        const float4 v2 = __ldcs(c2 + q);
        const float4 u0 = __ldg(d0 + q);
        const float4 u1 = __ldg(d1 + q);
        const float4 u2 = __ldg(d2 + q);
        float4 o;
        o.x = a0 * v0.x + a1 * v1.x + a2 * v2.x + bias;
        o.y = a0 * v0.y + a1 * v1.y + a2 * v2.y + bias;
        o.z = a0 * v0.z + a1 * v1.z + a2 * v2.z + bias;
        o.w = a0 * v0.w + a1 * v1.w + a2 * v2.w + bias;
        __stcs(o0 + q, o);
        float4 r;
        r.x = b0 * u0.x + b1 * u1.x + b2 * u2.x + rbias;
        r.y = b0 * u0.y + b1 * u1.y + b2 * u2.y + rbias;
        r.z = b0 * u0.z + b1 * u1.z + b2 * u2.z + rbias;
        r.w = b0 * u0.w + b1 * u1.w + b2 * u2.w + rbias;
        __stcs(o1 + q, r);
    }
}

// ---------------------------------------------------------------------------
extern "C" void kernel_launch(void* const* d_in, const int* in_sizes, int n_in,
                              void* d_out, int out_size) {
    const float* x      = (const float*)d_in[0];
    const int*   dates  = (const int*)d_in[1];
    const float* thetas = (const float*)d_in[2];
    float* out = (float*)d_out;
    float* xp  = out + OUT_ELEMS;

    k_translate_minmax<<<NPLANES * SLABS, 256>>>(x, dates, thetas, out);
    k_slice_ref<<<NIMG * SSLABS, 256>>>(x, xp);
}